// round 1
// baseline (speedup 1.0000x reference)
#include <cuda_runtime.h>
#include <math.h>

#define Bq  16
#define Nq  512
#define Mq  256
#define CCH 4     // NC+1 semantic channels
#define NCL 3     // background class id

// ---------------- scratch (no allocations allowed) ----------------
__device__ float  g_cost[Bq * Mq * Nq];   // cost^T: [b][m(gt row)][n(pred col)]
__device__ float  g_minc[Bq * Mq];        // min_n cdist per (b,m)
__device__ int    g_pred[Bq * Mq];        // pred vertex for each gt point
__device__ int    g_sgt [Bq * Nq];        // semantics_gt (int)
__device__ double g_acc [4];              // 0:softplus sum 1:matches-gather sum 2:logp sum 3:minc sum

// ---------------- helpers ----------------
__device__ __forceinline__ double block_reduce_add(double v) {
    __shared__ double sm[32];
    int lane = threadIdx.x & 31, w = threadIdx.x >> 5;
    #pragma unroll
    for (int o = 16; o > 0; o >>= 1) v += __shfl_down_sync(0xffffffffu, v, o);
    if (lane == 0) sm[w] = v;
    __syncthreads();
    int nw = (blockDim.x + 31) >> 5;
    v = (w == 0 && lane < nw) ? sm[lane] : 0.0;
    if (w == 0) {
        #pragma unroll
        for (int o = 16; o > 0; o >>= 1) v += __shfl_down_sync(0xffffffffu, v, o);
    }
    return v; // valid in thread 0
}

// ---------------- K0: zero accumulators ----------------
__global__ void k_zero_acc() {
    if (threadIdx.x < 4) g_acc[threadIdx.x] = 0.0;
}

// ---------------- K1: cost matrix + per-(b,m) min cdist ----------------
// grid = Bq*Mq blocks, 512 threads (one per pred vertex n)
__global__ void k_cost(const float* __restrict__ positions,
                       const float* __restrict__ semantics,
                       const float* __restrict__ pts_gt,
                       const int*   __restrict__ pts_type) {
    int bm = blockIdx.x;
    int b = bm / Mq, m = bm - b * Mq;
    int n = threadIdx.x;

    // normalized GT point: (p + bound) / (2*bound)
    float gx = (pts_gt[(b * Mq + m) * 2 + 0] + 30.0f) / 60.0f;
    float gy = (pts_gt[(b * Mq + m) * 2 + 1] + 15.0f) / 30.0f;
    // normalized prediction: p / (nx - 1)
    float px = positions[((size_t)b * Nq + n) * 2 + 0] / 399.0f;
    float py = positions[((size_t)b * Nq + n) * 2 + 1] / 199.0f;

    float dx = px - gx, dy = py - gy;
    float d2 = __fadd_rn(__fmul_rn(dx, dx), __fmul_rn(dy, dy));
    float c  = sqrtf(d2);

    int   t  = pts_type[b * Mq + m];
    float s  = semantics[((size_t)b * CCH + t) * Nq + n];
    // cost = 5*cdist + (-logp); fixed rounding, no FMA contraction
    g_cost[(size_t)bm * Nq + n] = __fadd_rn(__fmul_rn(5.0f, c), -s);

    // block min of cdist for cdist_mean
    __shared__ float sm[32];
    float v = c;
    int lane = threadIdx.x & 31, w = threadIdx.x >> 5;
    #pragma unroll
    for (int o = 16; o > 0; o >>= 1) v = fminf(v, __shfl_down_sync(0xffffffffu, v, o));
    if (lane == 0) sm[w] = v;
    __syncthreads();
    if (w == 0) {
        v = (lane < 16) ? sm[lane] : 3.0e38f;
        #pragma unroll
        for (int o = 16; o > 0; o >>= 1) v = fminf(v, __shfl_down_sync(0xffffffffu, v, o));
        if (lane == 0) g_minc[bm] = v;
    }
}

// ---------------- K2: Jonker-Volgenant LAP, exact replica of reference ----------------
// grid = Bq blocks, 512 threads (one per column / pred vertex)
__global__ void k_lap() {
    __shared__ double s_short[Nq];
    __shared__ double s_v[Nq];
    __shared__ double s_u[Mq];
    __shared__ int    s_pred[Nq];
    __shared__ int    s_r4c[Nq];
    __shared__ int    s_c4r[Mq];
    __shared__ unsigned char s_vis[Nq];
    __shared__ double w_val[16];
    __shared__ int    w_idx[16];
    __shared__ int    s_i, s_sink;
    __shared__ double s_min;

    const int b = blockIdx.x, t = threadIdx.x;
    const float* __restrict__ cost = g_cost + (size_t)b * Mq * Nq;
    const double DINF = INFINITY;

    s_v[t] = 0.0; s_r4c[t] = -1;
    if (t < Mq) { s_u[t] = 0.0; s_c4r[t] = -1; }
    __syncthreads();

    for (int cur = 0; cur < Mq; cur++) {
        s_short[t] = DINF; s_pred[t] = -1; s_vis[t] = 0;
        if (t == 0) { s_i = cur; s_sink = -1; s_min = 0.0; }
        __syncthreads();

        while (true) {
            int    i  = s_i;
            double mv = s_min;
            double val;
            if (!s_vis[t]) {
                // d = ((minval + cost[i][j]) - u[i]) - v[j], float64 exactly like numpy
                double d = ((mv + (double)cost[(size_t)i * Nq + t]) - s_u[i]) - s_v[t];
                if (d < s_short[t]) { s_short[t] = d; s_pred[t] = i; }
                val = s_short[t];
            } else {
                val = DINF;
            }
            // warp (val,idx) min with first-index tie-break
            int idx = t;
            #pragma unroll
            for (int o = 16; o > 0; o >>= 1) {
                double v2 = __shfl_down_sync(0xffffffffu, val, o);
                int    i2 = __shfl_down_sync(0xffffffffu, idx, o);
                if (v2 < val || (v2 == val && i2 < idx)) { val = v2; idx = i2; }
            }
            if ((t & 31) == 0) { w_val[t >> 5] = val; w_idx[t >> 5] = idx; }
            __syncthreads();
            if (t == 0) {
                double bv = w_val[0]; int bj = w_idx[0];
                #pragma unroll
                for (int w = 1; w < 16; w++) {
                    double v2 = w_val[w]; int i2 = w_idx[w];
                    if (v2 < bv || (v2 == bv && i2 < bj)) { bv = v2; bj = i2; }
                }
                s_min   = bv;          // == shortest[j]
                s_vis[bj] = 1;
                int r = s_r4c[bj];
                if (r < 0) s_sink = bj; else s_i = r;
            }
            __syncthreads();
            if (s_sink >= 0) break;
        }

        // dual updates (before augmenting; row4col still old)
        double mv  = s_min;
        int    snk = s_sink;
        if (t == 0) s_u[cur] += mv;
        if (s_vis[t]) {
            if (t != snk) {
                int r = s_r4c[t];           // distinct previously-assigned rows
                s_u[r] += mv - s_short[t];
            }
            s_v[t] += s_short[t] - mv;
        }
        __syncthreads();

        // augment along predecessor chain (serial)
        if (t == 0) {
            int j = snk;
            while (j != -1) {
                int i  = s_pred[j];
                s_r4c[j] = i;
                int nx = s_c4r[i];
                s_c4r[i] = j;
                j = nx;
            }
        }
        __syncthreads();
    }

    if (t < Mq) g_pred[b * Mq + t] = s_c4r[t];
}

// ---------------- K3: zero matches_gt, softplus sum, default semantics_gt ----------------
__global__ void k_fill(const float* __restrict__ matches, float* __restrict__ out_m) {
    const long long total  = (long long)Bq * Nq * Nq;
    const long long stride = (long long)gridDim.x * blockDim.x;
    long long idx = (long long)blockIdx.x * blockDim.x + threadIdx.x;

    double local = 0.0;
    for (long long i = idx; i < total; i += stride) {
        float x  = matches[i];
        float sp = (x > 0.0f) ? (x + log1pf(expf(-x))) : log1pf(expf(x));
        local += (double)sp;
        out_m[i] = 0.0f;
    }
    for (long long i = idx; i < Bq * Nq; i += stride) g_sgt[i] = NCL;

    double bsum = block_reduce_add(local);
    if (threadIdx.x == 0) atomicAdd(&g_acc[0], bsum);
}

// ---------------- K4: scatter matches_gt edges + semantics_gt + gather sum ----------------
__global__ void k_scatter(const float* __restrict__ matches,
                          const int*   __restrict__ pts_ins,
                          const int*   __restrict__ pts_type,
                          float* __restrict__ out_m) {
    int id = blockIdx.x * blockDim.x + threadIdx.x;
    double add = 0.0;
    if (id < Bq * Mq) {
        int b = id / Mq, m = id - b * Mq;
        int p = g_pred[id];
        g_sgt[b * Nq + p] = pts_type[id];
        if (m + 1 < Mq && pts_ins[id] == pts_ins[id + 1]) {
            int q = g_pred[id + 1];
            size_t e1 = ((size_t)b * Nq + p) * Nq + q;
            size_t e2 = ((size_t)b * Nq + q) * Nq + p;
            out_m[e1] = 1.0f;
            out_m[e2] = 1.0f;
            add = (double)matches[e1] + (double)matches[e2];
        }
    }
    double bsum = block_reduce_add(add);
    if (threadIdx.x == 0 && bsum != 0.0) atomicAdd(&g_acc[1], bsum);
}

// ---------------- K5: semantics_gt output + logp sum + minc sum ----------------
__global__ void k_sem(const float* __restrict__ semantics, float* __restrict__ out_s) {
    int id = blockIdx.x * blockDim.x + threadIdx.x;
    double lp = 0.0, mc = 0.0;
    if (id < Bq * Nq) {
        int b = id / Nq, n = id - b * Nq;
        int sg = g_sgt[id];
        out_s[id] = (float)sg;
        lp = (double)semantics[((size_t)b * CCH + sg) * Nq + n];
    }
    if (id < Bq * Mq) mc = (double)g_minc[id];

    double s1 = block_reduce_add(lp);
    __syncthreads();
    double s2 = block_reduce_add(mc);
    if (threadIdx.x == 0) {
        atomicAdd(&g_acc[2], s1);
        atomicAdd(&g_acc[3], s2);
    }
}

// ---------------- K6: finalize scalars ----------------
__global__ void k_final(float* __restrict__ out) {
    if (threadIdx.x == 0) {
        out[0] = (float)(g_acc[3] / (double)(Bq * Mq));
        out[1] = (float)((g_acc[0] - g_acc[1]) / ((double)Bq * Nq * Nq));
        out[2] = (float)(-g_acc[2] / (double)(Bq * Nq));
    }
}

// ---------------- launch ----------------
extern "C" void kernel_launch(void* const* d_in, const int* in_sizes, int n_in,
                              void* d_out, int out_size) {
    const float* matches   = (const float*)d_in[0];
    const float* positions = (const float*)d_in[1];
    const float* semantics = (const float*)d_in[2];
    // d_in[3] = masks (all ones, unused)
    const float* pts_gt    = (const float*)d_in[4];
    const int*   pts_ins   = (const int*)d_in[5];
    const int*   pts_type  = (const int*)d_in[6];

    float* out    = (float*)d_out;
    float* out_m  = out + 3;
    float* out_s  = out + 3 + (size_t)Bq * Nq * Nq;

    k_zero_acc<<<1, 32>>>();
    k_cost<<<Bq * Mq, Nq>>>(positions, semantics, pts_gt, pts_type);
    k_lap<<<Bq, Nq>>>();
    k_fill<<<1024, 256>>>(matches, out_m);
    k_scatter<<<(Bq * Mq + 255) / 256, 256>>>(matches, pts_ins, pts_type, out_m);
    k_sem<<<(Bq * Nq + 255) / 256, 256>>>(semantics, out_s);
    k_final<<<1, 1>>>(out);
}